// round 16
// baseline (speedup 1.0000x reference)
#include <cuda_runtime.h>
#include <cuda_fp16.h>
#include <cstdint>
#include <math.h>

// ---------------- problem constants ----------------
#define T_TOK 8192
#define D_DIM 1024
#define F_DIM 4096
#define E_NUM 8

// ---------------- tiling ----------------
#define BM 128
#define BK 32                    // halves per k-tile (2 mma k-steps)
#define KSTR 40                  // smem row stride in halves (32 + 8 pad)
#define A_BYTES (BM * KSTR * 2)  // 10240

#define NSTAGE 5

// up: two B tiles of 64 rows ([n][k])
#define UPB_BYTES (64 * KSTR * 2)            // 5120
#define UP_B0_OFF A_BYTES
#define UP_B1_OFF (A_BYTES + UPB_BYTES)
#define UP_STAGE  (A_BYTES + 2 * UPB_BYTES)  // 20480
#define UP_SMEM   (NSTAGE * UP_STAGE)        // 102400 (5-stage pipeline)

// down: one B tile of 128 rows
#define DN_B_OFF A_BYTES
#define DN_STAGE (A_BYTES + BM * KSTR * 2)   // 20480
#define DN_SMEM  (NSTAGE * DN_STAGE)         // 102400

// ---------------- scratch (device globals; no allocations) ----------------
__device__ __half g_h[(size_t)2 * T_TOK * F_DIM];           // fp16 hidden
__device__ __half g_xh[(size_t)T_TOK * D_DIM];              // fp16 inputs
__device__ __half g_wi0t[(size_t)E_NUM * D_DIM * F_DIM];    // wi0^T : [e][f][d]
__device__ __half g_wi1t[(size_t)E_NUM * D_DIM * F_DIM];    // wi1^T : [e][f][d]
__device__ __half g_wot[(size_t)E_NUM * F_DIM * D_DIM];     // wo^T  : [e][d][f]
__device__ int    g_entries[E_NUM * T_TOK];
__device__ int    g_cnt[E_NUM];
__device__ float  g_w[2 * T_TOK];

// ---------------- helpers ----------------
__device__ __forceinline__ uint32_t smem_u32(const void* p) {
    uint32_t a;
    asm("{ .reg .u64 t; cvta.to.shared.u64 t, %1; cvt.u32.u64 %0, t; }" : "=r"(a) : "l"(p));
    return a;
}

#define CPA16(dst, src) \
    asm volatile("cp.async.cg.shared.global [%0], [%1], 16;" :: "r"(dst), "l"(src) : "memory")
#define CP_COMMIT() asm volatile("cp.async.commit_group;" ::: "memory")
#define CP_WAIT3()  asm volatile("cp.async.wait_group 3;" ::: "memory")

// non-transposed ldmatrix x4: 4 8x8 b16 matrices, k-contiguous rows
__device__ __forceinline__ void ldsm4(uint32_t r[4], uint32_t a) {
    asm volatile("ldmatrix.sync.aligned.m8n8.x4.shared.b16 {%0,%1,%2,%3}, [%4];"
                 : "=r"(r[0]), "=r"(r[1]), "=r"(r[2]), "=r"(r[3]) : "r"(a) : "memory");
}

__device__ __forceinline__ void mma16(float c[4], const uint32_t a[4], uint32_t b0, uint32_t b1) {
    asm volatile(
        "mma.sync.aligned.m16n8k16.row.col.f32.f16.f16.f32 "
        "{%0,%1,%2,%3}, {%4,%5,%6,%7}, {%8,%9}, {%0,%1,%2,%3};"
        : "+f"(c[0]), "+f"(c[1]), "+f"(c[2]), "+f"(c[3])
        : "r"(a[0]), "r"(a[1]), "r"(a[2]), "r"(a[3]), "r"(b0), "r"(b1));
}

// ---------------- merged fp32 -> fp16 transpose for all 3 weight tensors ----------------
// Also resets g_cnt (runs before router).
__global__ void transpose_all_kernel(const float* __restrict__ wi0,
                                     const float* __restrict__ wi1,
                                     const float* __restrict__ wo,
                                     __half* __restrict__ d0,
                                     __half* __restrict__ d1,
                                     __half* __restrict__ d2) {
    if (blockIdx.x == 0 && blockIdx.y == 0 && threadIdx.y == 0 && threadIdx.x < E_NUM)
        g_cnt[threadIdx.x] = 0;

    __shared__ __half tile[32][66];   // [c][r]; conflict-free both phases
    const float* s;
    __half* d;
    int R, C;
    int which = blockIdx.y;
    if (which == 0)      { s = wi0; d = d0; R = D_DIM; C = F_DIM; }
    else if (which == 1) { s = wi1; d = d1; R = D_DIM; C = F_DIM; }
    else                 { s = wo;  d = d2; R = F_DIM; C = D_DIM; }

    int tiles_c = C >> 5;                 // C/32
    int per_e = tiles_c * (R >> 6);       // 2048 for both shapes
    int e  = blockIdx.x / per_e;
    int t  = blockIdx.x % per_e;
    int c0 = (t % tiles_c) * 32;
    int r0 = (t / tiles_c) * 64;
    s += (size_t)e * R * C;
    d += (size_t)e * R * C;

    int tx = threadIdx.x, ty = threadIdx.y;   // (32, 8)
#pragma unroll
    for (int k = 0; k < 8; k++) {
        int r = ty + 8 * k;               // 0..63
        tile[tx][r] = __float2half_rn(s[(size_t)(r0 + r) * C + c0 + tx]);
    }
    __syncthreads();
#pragma unroll
    for (int k = 0; k < 4; k++) {
        int c = ty + 8 * k;               // 0..31
        __half2 v = *(__half2*)&tile[c][2 * tx];
        *(__half2*)&d[(size_t)(c0 + c) * R + r0 + 2 * tx] = v;
    }
}

// ---------------- kernel 1: router (warp/token) + x fp16 conversion + out zeroing ----------------
__global__ void router_kernel(const float* __restrict__ x, const float* __restrict__ gw,
                              float* __restrict__ out) {
    // zero the output buffer (8 float4 per thread, coalesced; out not read until dn)
    {
        size_t base = ((size_t)blockIdx.x * blockDim.x + threadIdx.x) * 8;
        float4 z = make_float4(0.f, 0.f, 0.f, 0.f);
#pragma unroll
        for (int q = 0; q < 8; q++) ((float4*)out)[base + q] = z;
    }

    int warp = (blockIdx.x * blockDim.x + threadIdx.x) >> 5;
    int lane = threadIdx.x & 31;
    if (warp >= T_TOK) return;
    const float* xr = x + (size_t)warp * D_DIM;

    float acc[E_NUM];
#pragma unroll
    for (int e = 0; e < E_NUM; e++) acc[e] = 0.f;

    for (int j = lane; j < D_DIM; j += 32) {
        float xv = xr[j];
        g_xh[(size_t)warp * D_DIM + j] = __float2half_rn(xv);
        const float4* gp = (const float4*)(gw + (size_t)j * E_NUM);
        float4 g0 = gp[0], g1 = gp[1];
        acc[0] += xv * g0.x; acc[1] += xv * g0.y; acc[2] += xv * g0.z; acc[3] += xv * g0.w;
        acc[4] += xv * g1.x; acc[5] += xv * g1.y; acc[6] += xv * g1.z; acc[7] += xv * g1.w;
    }
#pragma unroll
    for (int e = 0; e < E_NUM; e++) {
#pragma unroll
        for (int o = 16; o > 0; o >>= 1)
            acc[e] += __shfl_down_sync(0xffffffffu, acc[e], o);
    }
    if (lane == 0) {
        float v0 = -1e30f, v1 = -1e30f;
        int e0 = 0, e1 = 0;
        for (int e = 0; e < E_NUM; e++) {
            float v = acc[e];
            if (v > v0)      { v1 = v0; e1 = e0; v0 = v; e0 = e; }
            else if (v > v1) { v1 = v;  e1 = e; }
        }
        float ex = expf(v1 - v0);
        float s  = 1.f / (1.f + ex);
        g_w[warp * 2 + 0] = s;
        g_w[warp * 2 + 1] = ex * s;
        int p0 = atomicAdd(&g_cnt[e0], 1);
        g_entries[e0 * T_TOK + p0] = warp * 2 + 0;
        int p1 = atomicAdd(&g_cnt[e1], 1);
        g_entries[e1 * T_TOK + p1] = warp * 2 + 1;
    }
}

// ---------------- kernel 2: up-projection (fp16 mma, dual-B, silu-gated) ----------------
// CTA: M=128 x 64 cols of EACH of wi0/wi1. Warp: 64x16 per matrix.
__global__ void __launch_bounds__(256, 2) ffn_up_kernel() {
    extern __shared__ char smem[];
    int e = blockIdx.z, mtile = blockIdx.y, ntile = blockIdx.x;
    int nt = g_cnt[e];
    if (mtile * BM >= nt) return;

    __shared__ int s_ent[BM];
    int tid = threadIdx.x;
    if (tid < BM) {
        int i = mtile * BM + tid;
        s_ent[tid] = (i < nt) ? g_entries[e * T_TOK + i] : -1;
    }
    __syncthreads();

    uint32_t dyn = smem_u32(smem);

    // A staging: thread -> (row, k-half): 2x16B
    int arow = tid >> 1, ah = (tid & 1) * 16;
    int ent0 = s_ent[arow];
    const __half* asrc = g_xh + (size_t)((ent0 >= 0) ? (ent0 >> 1) : 0) * D_DIM + ah;
    uint32_t adoff = (uint32_t)(arow * (KSTR * 2) + ah * 2);

    // B staging: thread -> (n-row, 8 halves): 1x16B per matrix. Tiles are [n][k].
    int brow = tid >> 2, bq = (tid & 3) * 8;
    const __half* b0src = g_wi0t + ((size_t)e * F_DIM + (size_t)ntile * 64 + brow) * D_DIM + bq;
    const __half* b1src = g_wi1t + ((size_t)e * F_DIM + (size_t)ntile * 64 + brow) * D_DIM + bq;
    uint32_t bdoff = (uint32_t)(brow * (KSTR * 2) + bq * 2);

    auto issue = [&](int i) {
        uint32_t sb = dyn + (i % NSTAGE) * UP_STAGE;
        int kt = i * BK;
        CPA16(sb + adoff, asrc + kt);
        CPA16(sb + adoff + 16, asrc + kt + 8);
        CPA16(sb + UP_B0_OFF + bdoff, b0src + kt);
        CPA16(sb + UP_B1_OFF + bdoff, b1src + kt);
        CP_COMMIT();
    };

    // fragment maps
    int lane = tid & 31, wid = tid >> 5;
    int g = lane >> 2, t4 = lane & 3;
    int mbase = (wid >> 2) * 64;
    int nbase = (wid & 3) * 16;

    // ldmatrix per-lane address components (quad = which 8x8 matrix)
    int quad = lane >> 3, lr = lane & 7;
    uint32_t a_loff = (uint32_t)(((mbase + (quad & 1) * 8 + lr) * KSTR + (quad & 2) * 4) * 2);
    uint32_t b_loff = (uint32_t)(((nbase + (quad & 2) * 4 + lr) * KSTR + (quad & 1) * 8) * 2);

    float cA[4][2][4], cB[4][2][4];
#pragma unroll
    for (int a = 0; a < 4; a++)
#pragma unroll
        for (int b = 0; b < 2; b++)
#pragma unroll
            for (int k = 0; k < 4; k++) { cA[a][b][k] = 0.f; cB[a][b][k] = 0.f; }

    const int NIT = D_DIM / BK;  // 32
    issue(0);
    issue(1);
    issue(2);
    issue(3);
    CP_WAIT3();          // group 0 complete
    __syncthreads();

    for (int i = 0; i < NIT; i++) {
        if (i + 4 < NIT) issue(i + 4); else CP_COMMIT();  // keep group count aligned

        uint32_t sb = dyn + (i % NSTAGE) * UP_STAGE;
#pragma unroll
        for (int ks = 0; ks < 2; ks++) {
            uint32_t a[4][4];
#pragma unroll
            for (int mt = 0; mt < 4; mt++)
                ldsm4(a[mt], sb + a_loff + (uint32_t)(mt * 16 * KSTR * 2) + ks * 32);
            uint32_t b0r[4], b1r[4];
            ldsm4(b0r, sb + UP_B0_OFF + b_loff + ks * 32);
            ldsm4(b1r, sb + UP_B1_OFF + b_loff + ks * 32);
#pragma unroll
            for (int mt = 0; mt < 4; mt++) {
                mma16(cA[mt][0], a[mt], b0r[0], b0r[1]);
                mma16(cA[mt][1], a[mt], b0r[2], b0r[3]);
                mma16(cB[mt][0], a[mt], b1r[0], b1r[1]);
                mma16(cB[mt][1], a[mt], b1r[2], b1r[3]);
            }
        }
        CP_WAIT3();      // group i+1 complete; i+2..i+4 may still fly
        __syncthreads();
    }

    // epilogue: h = silu(cA) * cB -> g_h (fp16)
#pragma unroll
    for (int mt = 0; mt < 4; mt++) {
        int r0 = mbase + mt * 16 + g;
#pragma unroll
        for (int q = 0; q < 2; q++) {
            size_t col = (size_t)ntile * 64 + nbase + q * 8 + t4 * 2;
            int e0 = s_ent[r0];
            if (e0 >= 0) {
                float a0 = cA[mt][q][0], a1 = cA[mt][q][1];
                float h0 = (a0 / (1.f + __expf(-a0))) * cB[mt][q][0];
                float h1 = (a1 / (1.f + __expf(-a1))) * cB[mt][q][1];
                *(__half2*)&g_h[(size_t)e0 * F_DIM + col] = __floats2half2_rn(h0, h1);
            }
            int e1 = s_ent[r0 + 8];
            if (e1 >= 0) {
                float a2 = cA[mt][q][2], a3 = cA[mt][q][3];
                float h2 = (a2 / (1.f + __expf(-a2))) * cB[mt][q][2];
                float h3 = (a3 / (1.f + __expf(-a3))) * cB[mt][q][3];
                *(__half2*)&g_h[(size_t)e1 * F_DIM + col] = __floats2half2_rn(h2, h3);
            }
        }
    }
}

// ---------------- kernel 3: down-projection (fp16 mma) + fused combine ----------------
// CTA: M=128 x N=128. Warp: 64x32.
__global__ void __launch_bounds__(256, 2) ffn_dn_kernel(float* __restrict__ out) {
    extern __shared__ char smem[];
    int e = blockIdx.z, mtile = blockIdx.y, ntile = blockIdx.x;
    int nt = g_cnt[e];
    if (mtile * BM >= nt) return;

    __shared__ int s_ent[BM];
    __shared__ float s_w[BM];
    int tid = threadIdx.x;
    if (tid < BM) {
        int i = mtile * BM + tid;
        int ent = (i < nt) ? g_entries[e * T_TOK + i] : -1;
        s_ent[tid] = ent;
        s_w[tid] = (ent >= 0) ? g_w[ent] : 0.f;
    }
    __syncthreads();

    uint32_t dyn = smem_u32(smem);

    // A staging (from g_h): 2x16B per thread
    int arow = tid >> 1, ah = (tid & 1) * 16;
    int ent0 = s_ent[arow];
    const __half* asrc = g_h + (size_t)((ent0 >= 0) ? ent0 : 0) * F_DIM + ah;
    uint32_t adoff = (uint32_t)(arow * (KSTR * 2) + ah * 2);

    // B staging (from wo^T [d][f]): tile [n=128][k=32], 2x16B per thread
    int brow = tid >> 1, bqh = (tid & 1) * 16;
    const __half* bsrc = g_wot + ((size_t)e * D_DIM + (size_t)ntile * 128 + brow) * F_DIM + bqh;
    uint32_t bdoff = (uint32_t)(DN_B_OFF + brow * (KSTR * 2) + bqh * 2);

    auto issue = [&](int i) {
        uint32_t sb = dyn + (i % NSTAGE) * DN_STAGE;
        int kt = i * BK;
        CPA16(sb + adoff, asrc + kt);
        CPA16(sb + adoff + 16, asrc + kt + 8);
        CPA16(sb + bdoff, bsrc + kt);
        CPA16(sb + bdoff + 16, bsrc + kt + 8);
        CP_COMMIT();
    };

    int lane = tid & 31, wid = tid >> 5;
    int g = lane >> 2, t4 = lane & 3;
    int mbase = (wid >> 2) * 64;
    int nbase = (wid & 3) * 32;

    int quad = lane >> 3, lr = lane & 7;
    uint32_t a_loff = (uint32_t)(((mbase + (quad & 1) * 8 + lr) * KSTR + (quad & 2) * 4) * 2);
    uint32_t b_loff = (uint32_t)(((nbase + (quad & 2) * 4 + lr) * KSTR + (quad & 1) * 8) * 2);

    float c[4][4][4];
#pragma unroll
    for (int a = 0; a < 4; a++)
#pragma unroll
        for (int b = 0; b < 4; b++)
#pragma unroll
            for (int k = 0; k < 4; k++) c[a][b][k] = 0.f;

    const int NIT = F_DIM / BK;  // 128
    issue(0);
    issue(1);
    issue(2);
    issue(3);
    CP_WAIT3();
    __syncthreads();

    for (int i = 0; i < NIT; i++) {
        if (i + 4 < NIT) issue(i + 4); else CP_COMMIT();

        uint32_t sb = dyn + (i % NSTAGE) * DN_STAGE;
#pragma unroll
        for (int ks = 0; ks < 2; ks++) {
            uint32_t a[4][4];
#pragma unroll
            for (int mt = 0; mt < 4; mt++)
                ldsm4(a[mt], sb + a_loff + (uint32_t)(mt * 16 * KSTR * 2) + ks * 32);
#pragma unroll
            for (int p = 0; p < 2; p++) {
                uint32_t br[4];   // {b0(q=2p), b1(q=2p), b0(q=2p+1), b1(q=2p+1)}
                ldsm4(br, sb + DN_B_OFF + b_loff + (uint32_t)(p * 16 * KSTR * 2) + ks * 32);
#pragma unroll
                for (int mt = 0; mt < 4; mt++) {
                    mma16(c[mt][2 * p],     a[mt], br[0], br[1]);
                    mma16(c[mt][2 * p + 1], a[mt], br[2], br[3]);
                }
            }
        }
        CP_WAIT3();
        __syncthreads();
    }

    // epilogue: out[tok] += w * o (2 commutative adds/element -> deterministic)
#pragma unroll
    for (int mt = 0; mt < 4; mt++) {
        int r0 = mbase + mt * 16 + g;
#pragma unroll
        for (int nq = 0; nq < 4; nq++) {
            size_t col = (size_t)ntile * 128 + nbase + nq * 8 + t4 * 2;
            int e0 = s_ent[r0];
            if (e0 >= 0) {
                float w = s_w[r0];
                float* o = out + (size_t)(e0 >> 1) * D_DIM + col;
                atomicAdd(o,     c[mt][nq][0] * w);
                atomicAdd(o + 1, c[mt][nq][1] * w);
            }
            int e1 = s_ent[r0 + 8];
            if (e1 >= 0) {
                float w = s_w[r0 + 8];
                float* o = out + (size_t)(e1 >> 1) * D_DIM + col;
                atomicAdd(o,     c[mt][nq][2] * w);
                atomicAdd(o + 1, c[mt][nq][3] * w);
            }
        }
    }
}

// ---------------- launcher ----------------
extern "C" void kernel_launch(void* const* d_in, const int* in_sizes, int n_in,
                              void* d_out, int out_size) {
    const float* x   = (const float*)d_in[0];
    const float* gw  = (const float*)d_in[1];
    const float* wi0 = (const float*)d_in[2];
    const float* wi1 = (const float*)d_in[3];
    const float* wo  = (const float*)d_in[4];
    float* out = (float*)d_out;

    cudaFuncSetAttribute(ffn_up_kernel, cudaFuncAttributeMaxDynamicSharedMemorySize, UP_SMEM);
    cudaFuncSetAttribute(ffn_dn_kernel, cudaFuncAttributeMaxDynamicSharedMemorySize, DN_SMEM);

    __half* wi0t; cudaGetSymbolAddress((void**)&wi0t, g_wi0t);
    __half* wi1t; cudaGetSymbolAddress((void**)&wi1t, g_wi1t);
    __half* wot;  cudaGetSymbolAddress((void**)&wot,  g_wot);

    dim3 tb(32, 8);
    dim3 tg(E_NUM * 2048, 3);   // all three weight tensors in one launch (+ cnt reset)
    transpose_all_kernel<<<tg, tb>>>(wi0, wi1, wo, wi0t, wi1t, wot);

    router_kernel<<<T_TOK / 8, 256>>>(x, gw, out);   // also zeroes out

    dim3 gup(F_DIM / 64, T_TOK / BM, E_NUM);    // (64, 64, 8)
    ffn_up_kernel<<<gup, 256, UP_SMEM>>>();

    dim3 gdn(D_DIM / 128, T_TOK / BM, E_NUM);   // (8, 64, 8)
    ffn_dn_kernel<<<gdn, 256, DN_SMEM>>>(out);
}

// round 17
// speedup vs baseline: 1.0769x; 1.0769x over previous
#include <cuda_runtime.h>
#include <cuda_fp16.h>
#include <cstdint>
#include <math.h>

// ---------------- problem constants ----------------
#define T_TOK 8192
#define D_DIM 1024
#define F_DIM 4096
#define E_NUM 8

// ---------------- tiling ----------------
#define BM 128
#define BK 32                    // halves per k-tile (2 mma k-steps)
#define KSTR 40                  // smem row stride in halves (32 + 8 pad)
#define A_BYTES (BM * KSTR * 2)  // 10240

// up: two B tiles of 64 rows ([n][k])
#define UPB_BYTES (64 * KSTR * 2)            // 5120
#define UP_B0_OFF A_BYTES
#define UP_B1_OFF (A_BYTES + UPB_BYTES)
#define UP_STAGE  (A_BYTES + 2 * UPB_BYTES)  // 20480
#define UP_SMEM   (4 * UP_STAGE)             // 81920 (4-stage pipeline)

// down: one B tile of 128 rows
#define DN_B_OFF A_BYTES
#define DN_STAGE (A_BYTES + BM * KSTR * 2)   // 20480
#define DN_SMEM  (4 * DN_STAGE)              // 81920

// ---------------- scratch (device globals; no allocations) ----------------
__device__ __half g_h[(size_t)2 * T_TOK * F_DIM];           // fp16 hidden
__device__ __half g_xh[(size_t)T_TOK * D_DIM];              // fp16 inputs
__device__ __half g_wi0t[(size_t)E_NUM * D_DIM * F_DIM];    // wi0^T : [e][f][d]
__device__ __half g_wi1t[(size_t)E_NUM * D_DIM * F_DIM];    // wi1^T : [e][f][d]
__device__ __half g_wot[(size_t)E_NUM * F_DIM * D_DIM];     // wo^T  : [e][d][f]
__device__ int    g_entries[E_NUM * T_TOK];
__device__ int    g_cnt[E_NUM];
__device__ float  g_w[2 * T_TOK];

// ---------------- helpers ----------------
__device__ __forceinline__ uint32_t smem_u32(const void* p) {
    uint32_t a;
    asm("{ .reg .u64 t; cvta.to.shared.u64 t, %1; cvt.u32.u64 %0, t; }" : "=r"(a) : "l"(p));
    return a;
}

#define CPA16(dst, src) \
    asm volatile("cp.async.cg.shared.global [%0], [%1], 16;" :: "r"(dst), "l"(src) : "memory")
#define CP_COMMIT() asm volatile("cp.async.commit_group;" ::: "memory")
#define CP_WAIT2()  asm volatile("cp.async.wait_group 2;" ::: "memory")

// non-transposed ldmatrix x4: 4 8x8 b16 matrices, k-contiguous rows
__device__ __forceinline__ void ldsm4(uint32_t r[4], uint32_t a) {
    asm volatile("ldmatrix.sync.aligned.m8n8.x4.shared.b16 {%0,%1,%2,%3}, [%4];"
                 : "=r"(r[0]), "=r"(r[1]), "=r"(r[2]), "=r"(r[3]) : "r"(a) : "memory");
}

__device__ __forceinline__ void mma16(float c[4], const uint32_t a[4], uint32_t b0, uint32_t b1) {
    asm volatile(
        "mma.sync.aligned.m16n8k16.row.col.f32.f16.f16.f32 "
        "{%0,%1,%2,%3}, {%4,%5,%6,%7}, {%8,%9}, {%0,%1,%2,%3};"
        : "+f"(c[0]), "+f"(c[1]), "+f"(c[2]), "+f"(c[3])
        : "r"(a[0]), "r"(a[1]), "r"(a[2]), "r"(a[3]), "r"(b0), "r"(b1));
}

// ---------------- merged fp32 -> fp16 transpose for all 3 weight tensors ----------------
// Also resets g_cnt (runs before router).
__global__ void transpose_all_kernel(const float* __restrict__ wi0,
                                     const float* __restrict__ wi1,
                                     const float* __restrict__ wo,
                                     __half* __restrict__ d0,
                                     __half* __restrict__ d1,
                                     __half* __restrict__ d2) {
    if (blockIdx.x == 0 && blockIdx.y == 0 && threadIdx.y == 0 && threadIdx.x < E_NUM)
        g_cnt[threadIdx.x] = 0;

    __shared__ __half tile[32][66];   // [c][r]; conflict-free both phases
    const float* s;
    __half* d;
    int R, C;
    int which = blockIdx.y;
    if (which == 0)      { s = wi0; d = d0; R = D_DIM; C = F_DIM; }
    else if (which == 1) { s = wi1; d = d1; R = D_DIM; C = F_DIM; }
    else                 { s = wo;  d = d2; R = F_DIM; C = D_DIM; }

    int tiles_c = C >> 5;                 // C/32
    int per_e = tiles_c * (R >> 6);       // 2048 for both shapes
    int e  = blockIdx.x / per_e;
    int t  = blockIdx.x % per_e;
    int c0 = (t % tiles_c) * 32;
    int r0 = (t / tiles_c) * 64;
    s += (size_t)e * R * C;
    d += (size_t)e * R * C;

    int tx = threadIdx.x, ty = threadIdx.y;   // (32, 8)
#pragma unroll
    for (int k = 0; k < 8; k++) {
        int r = ty + 8 * k;               // 0..63
        tile[tx][r] = __float2half_rn(s[(size_t)(r0 + r) * C + c0 + tx]);
    }
    __syncthreads();
#pragma unroll
    for (int k = 0; k < 4; k++) {
        int c = ty + 8 * k;               // 0..31
        __half2 v = *(__half2*)&tile[c][2 * tx];
        *(__half2*)&d[(size_t)(c0 + c) * R + r0 + 2 * tx] = v;
    }
}

// ---------------- kernel 1: router (warp/token) + x fp16 conversion + out zeroing ----------------
__global__ void router_kernel(const float* __restrict__ x, const float* __restrict__ gw,
                              float* __restrict__ out) {
    // zero the output buffer (8 float4 per thread, coalesced; out not read until dn)
    {
        size_t base = ((size_t)blockIdx.x * blockDim.x + threadIdx.x) * 8;
        float4 z = make_float4(0.f, 0.f, 0.f, 0.f);
#pragma unroll
        for (int q = 0; q < 8; q++) ((float4*)out)[base + q] = z;
    }

    int warp = (blockIdx.x * blockDim.x + threadIdx.x) >> 5;
    int lane = threadIdx.x & 31;
    if (warp >= T_TOK) return;
    const float* xr = x + (size_t)warp * D_DIM;

    float acc[E_NUM];
#pragma unroll
    for (int e = 0; e < E_NUM; e++) acc[e] = 0.f;

    for (int j = lane; j < D_DIM; j += 32) {
        float xv = xr[j];
        g_xh[(size_t)warp * D_DIM + j] = __float2half_rn(xv);
        const float4* gp = (const float4*)(gw + (size_t)j * E_NUM);
        float4 g0 = gp[0], g1 = gp[1];
        acc[0] += xv * g0.x; acc[1] += xv * g0.y; acc[2] += xv * g0.z; acc[3] += xv * g0.w;
        acc[4] += xv * g1.x; acc[5] += xv * g1.y; acc[6] += xv * g1.z; acc[7] += xv * g1.w;
    }
#pragma unroll
    for (int e = 0; e < E_NUM; e++) {
#pragma unroll
        for (int o = 16; o > 0; o >>= 1)
            acc[e] += __shfl_down_sync(0xffffffffu, acc[e], o);
    }
    if (lane == 0) {
        float v0 = -1e30f, v1 = -1e30f;
        int e0 = 0, e1 = 0;
        for (int e = 0; e < E_NUM; e++) {
            float v = acc[e];
            if (v > v0)      { v1 = v0; e1 = e0; v0 = v; e0 = e; }
            else if (v > v1) { v1 = v;  e1 = e; }
        }
        float ex = expf(v1 - v0);
        float s  = 1.f / (1.f + ex);
        g_w[warp * 2 + 0] = s;
        g_w[warp * 2 + 1] = ex * s;
        int p0 = atomicAdd(&g_cnt[e0], 1);
        g_entries[e0 * T_TOK + p0] = warp * 2 + 0;
        int p1 = atomicAdd(&g_cnt[e1], 1);
        g_entries[e1 * T_TOK + p1] = warp * 2 + 1;
    }
}

// ---------------- kernel 2: up-projection (fp16 mma, dual-B, silu-gated) ----------------
// CTA: M=128 x 64 cols of EACH of wi0/wi1. Warp: 64x16 per matrix.
__global__ void __launch_bounds__(256, 2) ffn_up_kernel() {
    extern __shared__ char smem[];
    int e = blockIdx.z, mtile = blockIdx.y, ntile = blockIdx.x;
    int nt = g_cnt[e];
    if (mtile * BM >= nt) return;

    __shared__ int s_ent[BM];
    int tid = threadIdx.x;
    if (tid < BM) {
        int i = mtile * BM + tid;
        s_ent[tid] = (i < nt) ? g_entries[e * T_TOK + i] : -1;
    }
    __syncthreads();

    uint32_t dyn = smem_u32(smem);

    // A staging: thread -> (row, k-half): 2x16B
    int arow = tid >> 1, ah = (tid & 1) * 16;
    int ent0 = s_ent[arow];
    const __half* asrc = g_xh + (size_t)((ent0 >= 0) ? (ent0 >> 1) : 0) * D_DIM + ah;
    uint32_t adoff = (uint32_t)(arow * (KSTR * 2) + ah * 2);

    // B staging: thread -> (n-row, 8 halves): 1x16B per matrix. Tiles are [n][k].
    int brow = tid >> 2, bq = (tid & 3) * 8;
    const __half* b0src = g_wi0t + ((size_t)e * F_DIM + (size_t)ntile * 64 + brow) * D_DIM + bq;
    const __half* b1src = g_wi1t + ((size_t)e * F_DIM + (size_t)ntile * 64 + brow) * D_DIM + bq;
    uint32_t bdoff = (uint32_t)(brow * (KSTR * 2) + bq * 2);

    auto issue = [&](int i) {
        uint32_t sb = dyn + (i & 3) * UP_STAGE;
        int kt = i * BK;
        CPA16(sb + adoff, asrc + kt);
        CPA16(sb + adoff + 16, asrc + kt + 8);
        CPA16(sb + UP_B0_OFF + bdoff, b0src + kt);
        CPA16(sb + UP_B1_OFF + bdoff, b1src + kt);
        CP_COMMIT();
    };

    // fragment maps
    int lane = tid & 31, wid = tid >> 5;
    int g = lane >> 2, t4 = lane & 3;
    int mbase = (wid >> 2) * 64;
    int nbase = (wid & 3) * 16;

    // ldmatrix per-lane address components (quad = which 8x8 matrix)
    int quad = lane >> 3, lr = lane & 7;
    uint32_t a_loff = (uint32_t)(((mbase + (quad & 1) * 8 + lr) * KSTR + (quad & 2) * 4) * 2);
    uint32_t b_loff = (uint32_t)(((nbase + (quad & 2) * 4 + lr) * KSTR + (quad & 1) * 8) * 2);

    float cA[4][2][4], cB[4][2][4];
#pragma unroll
    for (int a = 0; a < 4; a++)
#pragma unroll
        for (int b = 0; b < 2; b++)
#pragma unroll
            for (int k = 0; k < 4; k++) { cA[a][b][k] = 0.f; cB[a][b][k] = 0.f; }

    const int NIT = D_DIM / BK;  // 32
    issue(0);
    issue(1);
    issue(2);
    CP_WAIT2();          // group 0 complete
    __syncthreads();

    for (int i = 0; i < NIT; i++) {
        if (i + 3 < NIT) issue(i + 3); else CP_COMMIT();  // keep group count aligned

        uint32_t sb = dyn + (i & 3) * UP_STAGE;
#pragma unroll
        for (int ks = 0; ks < 2; ks++) {
            uint32_t a[4][4];
#pragma unroll
            for (int mt = 0; mt < 4; mt++)
                ldsm4(a[mt], sb + a_loff + (uint32_t)(mt * 16 * KSTR * 2) + ks * 32);
            uint32_t b0r[4], b1r[4];
            ldsm4(b0r, sb + UP_B0_OFF + b_loff + ks * 32);
            ldsm4(b1r, sb + UP_B1_OFF + b_loff + ks * 32);
#pragma unroll
            for (int mt = 0; mt < 4; mt++) {
                mma16(cA[mt][0], a[mt], b0r[0], b0r[1]);
                mma16(cA[mt][1], a[mt], b0r[2], b0r[3]);
                mma16(cB[mt][0], a[mt], b1r[0], b1r[1]);
                mma16(cB[mt][1], a[mt], b1r[2], b1r[3]);
            }
        }
        CP_WAIT2();      // group i+1 complete; i+2, i+3 may still fly
        __syncthreads();
    }

    // epilogue: h = silu(cA) * cB -> g_h (fp16)
#pragma unroll
    for (int mt = 0; mt < 4; mt++) {
        int r0 = mbase + mt * 16 + g;
#pragma unroll
        for (int q = 0; q < 2; q++) {
            size_t col = (size_t)ntile * 64 + nbase + q * 8 + t4 * 2;
            int e0 = s_ent[r0];
            if (e0 >= 0) {
                float a0 = cA[mt][q][0], a1 = cA[mt][q][1];
                float h0 = (a0 / (1.f + __expf(-a0))) * cB[mt][q][0];
                float h1 = (a1 / (1.f + __expf(-a1))) * cB[mt][q][1];
                *(__half2*)&g_h[(size_t)e0 * F_DIM + col] = __floats2half2_rn(h0, h1);
            }
            int e1 = s_ent[r0 + 8];
            if (e1 >= 0) {
                float a2 = cA[mt][q][2], a3 = cA[mt][q][3];
                float h2 = (a2 / (1.f + __expf(-a2))) * cB[mt][q][2];
                float h3 = (a3 / (1.f + __expf(-a3))) * cB[mt][q][3];
                *(__half2*)&g_h[(size_t)e1 * F_DIM + col] = __floats2half2_rn(h2, h3);
            }
        }
    }
}

// ---------------- kernel 3: down-projection (fp16 mma) + fused combine ----------------
// CTA: M=128 x N=128. Warp: 64x32.
__global__ void __launch_bounds__(256, 2) ffn_dn_kernel(float* __restrict__ out) {
    extern __shared__ char smem[];
    int e = blockIdx.z, mtile = blockIdx.y, ntile = blockIdx.x;
    int nt = g_cnt[e];
    if (mtile * BM >= nt) return;

    __shared__ int s_ent[BM];
    __shared__ float s_w[BM];
    int tid = threadIdx.x;
    if (tid < BM) {
        int i = mtile * BM + tid;
        int ent = (i < nt) ? g_entries[e * T_TOK + i] : -1;
        s_ent[tid] = ent;
        s_w[tid] = (ent >= 0) ? g_w[ent] : 0.f;
    }
    __syncthreads();

    uint32_t dyn = smem_u32(smem);

    // A staging (from g_h): 2x16B per thread
    int arow = tid >> 1, ah = (tid & 1) * 16;
    int ent0 = s_ent[arow];
    const __half* asrc = g_h + (size_t)((ent0 >= 0) ? ent0 : 0) * F_DIM + ah;
    uint32_t adoff = (uint32_t)(arow * (KSTR * 2) + ah * 2);

    // B staging (from wo^T [d][f]): tile [n=128][k=32], 2x16B per thread
    int brow = tid >> 1, bqh = (tid & 1) * 16;
    const __half* bsrc = g_wot + ((size_t)e * D_DIM + (size_t)ntile * 128 + brow) * F_DIM + bqh;
    uint32_t bdoff = (uint32_t)(DN_B_OFF + brow * (KSTR * 2) + bqh * 2);

    auto issue = [&](int i) {
        uint32_t sb = dyn + (i & 3) * DN_STAGE;
        int kt = i * BK;
        CPA16(sb + adoff, asrc + kt);
        CPA16(sb + adoff + 16, asrc + kt + 8);
        CPA16(sb + bdoff, bsrc + kt);
        CPA16(sb + bdoff + 16, bsrc + kt + 8);
        CP_COMMIT();
    };

    int lane = tid & 31, wid = tid >> 5;
    int g = lane >> 2, t4 = lane & 3;
    int mbase = (wid >> 2) * 64;
    int nbase = (wid & 3) * 32;

    int quad = lane >> 3, lr = lane & 7;
    uint32_t a_loff = (uint32_t)(((mbase + (quad & 1) * 8 + lr) * KSTR + (quad & 2) * 4) * 2);
    uint32_t b_loff = (uint32_t)(((nbase + (quad & 2) * 4 + lr) * KSTR + (quad & 1) * 8) * 2);

    float c[4][4][4];
#pragma unroll
    for (int a = 0; a < 4; a++)
#pragma unroll
        for (int b = 0; b < 4; b++)
#pragma unroll
            for (int k = 0; k < 4; k++) c[a][b][k] = 0.f;

    const int NIT = F_DIM / BK;  // 128
    issue(0);
    issue(1);
    issue(2);
    CP_WAIT2();
    __syncthreads();

    for (int i = 0; i < NIT; i++) {
        if (i + 3 < NIT) issue(i + 3); else CP_COMMIT();

        uint32_t sb = dyn + (i & 3) * DN_STAGE;
#pragma unroll
        for (int ks = 0; ks < 2; ks++) {
            uint32_t a[4][4];
#pragma unroll
            for (int mt = 0; mt < 4; mt++)
                ldsm4(a[mt], sb + a_loff + (uint32_t)(mt * 16 * KSTR * 2) + ks * 32);
#pragma unroll
            for (int p = 0; p < 2; p++) {
                uint32_t br[4];   // {b0(q=2p), b1(q=2p), b0(q=2p+1), b1(q=2p+1)}
                ldsm4(br, sb + DN_B_OFF + b_loff + (uint32_t)(p * 16 * KSTR * 2) + ks * 32);
#pragma unroll
                for (int mt = 0; mt < 4; mt++) {
                    mma16(c[mt][2 * p],     a[mt], br[0], br[1]);
                    mma16(c[mt][2 * p + 1], a[mt], br[2], br[3]);
                }
            }
        }
        CP_WAIT2();
        __syncthreads();
    }

    // epilogue: out[tok] += w * o (2 commutative adds/element -> deterministic)
#pragma unroll
    for (int mt = 0; mt < 4; mt++) {
        int r0 = mbase + mt * 16 + g;
#pragma unroll
        for (int nq = 0; nq < 4; nq++) {
            size_t col = (size_t)ntile * 128 + nbase + nq * 8 + t4 * 2;
            int e0 = s_ent[r0];
            if (e0 >= 0) {
                float w = s_w[r0];
                float* o = out + (size_t)(e0 >> 1) * D_DIM + col;
                atomicAdd(o,     c[mt][nq][0] * w);
                atomicAdd(o + 1, c[mt][nq][1] * w);
            }
            int e1 = s_ent[r0 + 8];
            if (e1 >= 0) {
                float w = s_w[r0 + 8];
                float* o = out + (size_t)(e1 >> 1) * D_DIM + col;
                atomicAdd(o,     c[mt][nq][2] * w);
                atomicAdd(o + 1, c[mt][nq][3] * w);
            }
        }
    }
}

// ---------------- launcher ----------------
extern "C" void kernel_launch(void* const* d_in, const int* in_sizes, int n_in,
                              void* d_out, int out_size) {
    const float* x   = (const float*)d_in[0];
    const float* gw  = (const float*)d_in[1];
    const float* wi0 = (const float*)d_in[2];
    const float* wi1 = (const float*)d_in[3];
    const float* wo  = (const float*)d_in[4];
    float* out = (float*)d_out;

    cudaFuncSetAttribute(ffn_up_kernel, cudaFuncAttributeMaxDynamicSharedMemorySize, UP_SMEM);
    cudaFuncSetAttribute(ffn_dn_kernel, cudaFuncAttributeMaxDynamicSharedMemorySize, DN_SMEM);

    __half* wi0t; cudaGetSymbolAddress((void**)&wi0t, g_wi0t);
    __half* wi1t; cudaGetSymbolAddress((void**)&wi1t, g_wi1t);
    __half* wot;  cudaGetSymbolAddress((void**)&wot,  g_wot);

    dim3 tb(32, 8);
    dim3 tg(E_NUM * 2048, 3);   // all three weight tensors in one launch (+ cnt reset)
    transpose_all_kernel<<<tg, tb>>>(wi0, wi1, wo, wi0t, wi1t, wot);

    router_kernel<<<T_TOK / 8, 256>>>(x, gw, out);   // also zeroes out

    dim3 gup(F_DIM / 64, T_TOK / BM, E_NUM);    // (64, 64, 8)
    ffn_up_kernel<<<gup, 256, UP_SMEM>>>();

    dim3 gdn(D_DIM / 128, T_TOK / BM, E_NUM);   // (8, 64, 8)
    ffn_dn_kernel<<<gdn, 256, DN_SMEM>>>(out);
}